// round 1
// baseline (speedup 1.0000x reference)
#include <cuda_runtime.h>
#include <cuda_bf16.h>
#include <mma.h>

#define B_SZ 64
#define T_SZ 2048
#define K_SZ 256      // U_dim == X_dim
#define UN   256      // units
#define M_SZ (B_SZ * T_SZ)   // 131072 GEMM rows

// ---------------- device scratch (no runtime allocation allowed) ----------------
__device__ float g_Ubias[B_SZ * UN];
__device__ float g_Zp[B_SZ * UN];
__device__ float g_Zi[B_SZ * UN];
__device__ float g_Zd[B_SZ * UN];
__device__ float g_I[B_SZ * UN];                       // I state: init I0, ends I_{T-1}
__device__ __nv_bfloat16 g_Xhi[(size_t)M_SZ * K_SZ];   // 67 MB
__device__ __nv_bfloat16 g_Xlo[(size_t)M_SZ * K_SZ];   // 67 MB
__device__ __nv_bfloat16 g_Beff[3 * K_SZ * UN];        // [W_hi ; W_hi ; W_lo]
__device__ float g_XWi[(size_t)M_SZ * UN];             // 134 MB

static __device__ __forceinline__ float softsign_exact(float z) {
    return z / (1.0f + fabsf(z));
}

// ---------------- prep: U_bias, Z_p/Z_i/Z_d, I0 (all exact fp32) ----------------
__global__ void prep_kernel(const float* __restrict__ U,
                            const float* __restrict__ R_z,
                            const float* __restrict__ b_z,
                            const float* __restrict__ R_0,
                            const float* __restrict__ b_0,
                            const float* __restrict__ R_b) {
    __shared__ float u[K_SZ];
    int b = blockIdx.x;
    for (int k = threadIdx.x; k < K_SZ; k += blockDim.x) u[k] = U[b * K_SZ + k];
    __syncthreads();

    // combined output columns: [0,256) -> U@R_b, [256,1024) -> U@R_z+b_z,
    // [1024,1280) -> I0 = (U@R_0+b_0)[:, :256]  ([1280,1536) = X0, unused)
    for (int c = threadIdx.x; c < 1536; c += blockDim.x) {
        if (c >= 1280) continue;  // X0 never affects Ys[-1] for T >= 2
        const float* M; int col; int ncol; float bias = 0.0f;
        if (c < 256)       { M = R_b; col = c;        ncol = 256; }
        else if (c < 1024) { M = R_z; col = c - 256;  ncol = 768; bias = b_z[col]; }
        else               { M = R_0; col = c - 1024; ncol = 512; bias = b_0[col]; }
        float acc = bias;
        #pragma unroll 8
        for (int k = 0; k < K_SZ; k++) acc = fmaf(u[k], M[k * ncol + col], acc);

        if (c < 256) {
            g_Ubias[b * UN + c] = acc;
        } else if (c < 1024) {
            int cc = c - 256;
            int un = cc / 3, which = cc % 3;   // reshape(B, units, 3)
            if (which == 0)      g_Zp[b * UN + un] = acc;
            else if (which == 1) g_Zi[b * UN + un] = acc;
            else                 g_Zd[b * UN + un] = acc;
        } else {
            g_I[b * UN + (c - 1024)] = acc;    // I0
        }
    }
}

// ---------------- W_i split -> B_eff = [W_hi ; W_hi ; W_lo] ----------------
__global__ void beff_kernel(const float* __restrict__ W_i) {
    int idx = blockIdx.x * blockDim.x + threadIdx.x;
    if (idx >= K_SZ * UN) return;
    float w = W_i[idx];
    __nv_bfloat16 hi = __float2bfloat16(w);
    __nv_bfloat16 lo = __float2bfloat16(w - __bfloat162float(hi));
    g_Beff[idx]                 = hi;
    g_Beff[K_SZ * UN + idx]     = hi;
    g_Beff[2 * K_SZ * UN + idx] = lo;
}

// ---------------- X -> (X_hi, X_lo) bf16 split ----------------
__global__ void convert_kernel(const float* __restrict__ X) {
    size_t i = (size_t)blockIdx.x * blockDim.x + threadIdx.x;
    size_t n4 = (size_t)M_SZ * K_SZ / 4;
    if (i >= n4) return;
    float4 x = reinterpret_cast<const float4*>(X)[i];
    __nv_bfloat16 h0 = __float2bfloat16(x.x);
    __nv_bfloat16 h1 = __float2bfloat16(x.y);
    __nv_bfloat16 h2 = __float2bfloat16(x.z);
    __nv_bfloat16 h3 = __float2bfloat16(x.w);
    __nv_bfloat162 hA; hA.x = h0; hA.y = h1;
    __nv_bfloat162 hB; hB.x = h2; hB.y = h3;
    __nv_bfloat162 lA;
    lA.x = __float2bfloat16(x.x - __bfloat162float(h0));
    lA.y = __float2bfloat16(x.y - __bfloat162float(h1));
    __nv_bfloat162 lB;
    lB.x = __float2bfloat16(x.z - __bfloat162float(h2));
    lB.y = __float2bfloat16(x.w - __bfloat162float(h3));
    reinterpret_cast<__nv_bfloat162*>(g_Xhi)[2 * i]     = hA;
    reinterpret_cast<__nv_bfloat162*>(g_Xhi)[2 * i + 1] = hB;
    reinterpret_cast<__nv_bfloat162*>(g_Xlo)[2 * i]     = lA;
    reinterpret_cast<__nv_bfloat162*>(g_Xlo)[2 * i + 1] = lB;
}

// ---------------- big GEMM: XWi = [Xhi|Xlo|Xhi] @ [Whi;Whi;Wlo] (K_eff=768) ----
#define BM 128
#define BN 256
#define BK 32
#define A_LD 40    // 32 + 8 pad (keeps 16B alignment: 40*2=80 bytes/row)
#define B_LD 264   // 256 + 8 pad (528 bytes/row)

__global__ void __launch_bounds__(512, 1) gemm_kernel() {
    using namespace nvcuda;
    __shared__ __align__(16) __nv_bfloat16 As[BM * A_LD];
    __shared__ __align__(16) __nv_bfloat16 Bs[BK * B_LD];

    int tid = threadIdx.x;
    int m0  = blockIdx.x * BM;
    int w   = tid >> 5;
    int wm  = w >> 2;      // 0..3  (rows of 32)
    int wn  = w & 3;       // 0..3  (cols of 64)

    wmma::fragment<wmma::accumulator, 16, 16, 16, float> acc[2][4];
    #pragma unroll
    for (int i = 0; i < 2; i++)
        #pragma unroll
        for (int j = 0; j < 4; j++)
            wmma::fill_fragment(acc[i][j], 0.0f);

    for (int kc = 0; kc < 3 * K_SZ; kc += BK) {
        int seg  = kc >> 8;          // 0:hi*Whi  1:lo*Whi  2:hi*Wlo
        int ksrc = kc & 255;
        const __nv_bfloat16* Asrc = (seg == 1) ? g_Xlo : g_Xhi;

        // stage A: 128 rows x 32 cols = 512 x uint4, one per thread
        {
            int row = tid >> 2, q = tid & 3;
            const uint4* src = reinterpret_cast<const uint4*>(
                Asrc + (size_t)(m0 + row) * K_SZ + ksrc) + q;
            *reinterpret_cast<uint4*>(&As[row * A_LD + q * 8]) = *src;
        }
        // stage B: 32 rows x 256 cols = 1024 x uint4, two per thread
        #pragma unroll
        for (int r2 = 0; r2 < 2; r2++) {
            int li = tid + r2 * 512;
            int row = li >> 5, q = li & 31;
            const uint4* src = reinterpret_cast<const uint4*>(
                g_Beff + (size_t)(kc + row) * UN) + q;
            *reinterpret_cast<uint4*>(&Bs[row * B_LD + q * 8]) = *src;
        }
        __syncthreads();

        #pragma unroll
        for (int kk = 0; kk < BK; kk += 16) {
            wmma::fragment<wmma::matrix_a, 16, 16, 16, __nv_bfloat16, wmma::row_major> a[2];
            wmma::fragment<wmma::matrix_b, 16, 16, 16, __nv_bfloat16, wmma::row_major> bf[4];
            #pragma unroll
            for (int i = 0; i < 2; i++)
                wmma::load_matrix_sync(a[i], &As[(wm * 32 + i * 16) * A_LD + kk], A_LD);
            #pragma unroll
            for (int j = 0; j < 4; j++)
                wmma::load_matrix_sync(bf[j], &Bs[kk * B_LD + wn * 64 + j * 16], B_LD);
            #pragma unroll
            for (int i = 0; i < 2; i++)
                #pragma unroll
                for (int j = 0; j < 4; j++)
                    wmma::mma_sync(acc[i][j], a[i], bf[j], acc[i][j]);
        }
        __syncthreads();
    }

    #pragma unroll
    for (int i = 0; i < 2; i++)
        #pragma unroll
        for (int j = 0; j < 4; j++)
            wmma::store_matrix_sync(
                &g_XWi[(size_t)(m0 + wm * 32 + i * 16) * UN + wn * 64 + j * 16],
                acc[i][j], UN, wmma::mem_row_major);
}

// ---------------- sequential softsign scan over T ----------------
#define SCAN_D 16
__global__ void scan_kernel() {
    int idx = blockIdx.x * blockDim.x + threadIdx.x;  // 16384 elements
    int b = idx >> 8, u = idx & 255;
    const float* __restrict__ p = g_XWi + (size_t)b * T_SZ * UN + u;
    float I = g_I[idx];

    float buf[SCAN_D];
    #pragma unroll
    for (int d = 0; d < SCAN_D; d++) buf[d] = p[(size_t)d * UN];

    for (int t0 = 0; t0 < T_SZ; t0 += SCAN_D) {
        #pragma unroll
        for (int d = 0; d < SCAN_D; d++) {
            float v = buf[d];
            int tn = t0 + d + SCAN_D;
            if (tn < T_SZ) buf[d] = p[(size_t)tn * UN];
            float z = I + v;
            I = __fdividef(z, 1.0f + fabsf(z));
        }
    }
    g_I[idx] = I;
}

// ---------------- epilogue: P, D (last step only) and Y ----------------
__global__ void epilogue_kernel(const float* __restrict__ X,
                                const float* __restrict__ W_p,
                                const float* __restrict__ W_d,
                                float* __restrict__ out) {
    int b = blockIdx.x;
    int u = threadIdx.x;
    __shared__ float xl[K_SZ];
    __shared__ float dx[K_SZ];
    const float* xlast = X + ((size_t)b * T_SZ + (T_SZ - 1)) * K_SZ;
    const float* xprev = X + ((size_t)b * T_SZ + (T_SZ - 2)) * K_SZ;
    for (int k = u; k < K_SZ; k += blockDim.x) {
        float a = xlast[k];
        xl[k] = a;
        dx[k] = a - xprev[k];
    }
    __syncthreads();

    float pacc = g_Ubias[b * UN + u];
    float dacc = 0.0f;
    #pragma unroll 8
    for (int k = 0; k < K_SZ; k++) {
        pacc = fmaf(xl[k], W_p[k * UN + u], pacc);
        dacc = fmaf(dx[k], W_d[k * UN + u], dacc);
    }
    float P  = softsign_exact(pacc);
    float Dv = softsign_exact(dacc);
    float I  = g_I[b * UN + u];
    out[b * UN + u] = g_Zp[b * UN + u] * P + g_Zi[b * UN + u] * I + g_Zd[b * UN + u] * Dv;
}

// ---------------- launcher ----------------
extern "C" void kernel_launch(void* const* d_in, const int* in_sizes, int n_in,
                              void* d_out, int out_size) {
    const float* U   = (const float*)d_in[0];
    const float* X   = (const float*)d_in[1];
    const float* R_z = (const float*)d_in[2];
    const float* b_z = (const float*)d_in[3];
    const float* R_0 = (const float*)d_in[4];
    const float* b_0 = (const float*)d_in[5];
    const float* R_b = (const float*)d_in[6];
    const float* W_p = (const float*)d_in[7];
    const float* W_i = (const float*)d_in[8];
    const float* W_d = (const float*)d_in[9];
    float* out = (float*)d_out;

    prep_kernel<<<B_SZ, 256>>>(U, R_z, b_z, R_0, b_0, R_b);
    beff_kernel<<<(K_SZ * UN + 255) / 256, 256>>>(W_i);
    {
        size_t n4 = (size_t)M_SZ * K_SZ / 4;
        convert_kernel<<<(unsigned)((n4 + 255) / 256), 256>>>(X);
    }
    gemm_kernel<<<M_SZ / BM, 512>>>();
    scan_kernel<<<128, 128>>>();
    epilogue_kernel<<<B_SZ, 256>>>(X, W_p, W_d, out);
}

// round 3
// speedup vs baseline: 1.2812x; 1.2812x over previous
#include <cuda_runtime.h>
#include <cuda_bf16.h>
#include <mma.h>
#include <cstdint>

#define B_SZ 64
#define T_SZ 2048
#define K_SZ 256      // U_dim == X_dim
#define UN   256      // units
#define M_SZ (B_SZ * T_SZ)   // 131072 GEMM rows

// ---------------- device scratch (no runtime allocation allowed) ----------------
__device__ float g_Ubias[B_SZ * UN];
__device__ float g_Zp[B_SZ * UN];
__device__ float g_Zi[B_SZ * UN];
__device__ float g_Zd[B_SZ * UN];
__device__ float g_I[B_SZ * UN];                        // I state: init I0, ends I_{T-1}
__device__ __nv_bfloat16 g_Ws[2][K_SZ][UN];             // [hi/lo][k][n]  W_i split
__device__ float g_XWi[(size_t)M_SZ * UN];              // 134 MB

static __device__ __forceinline__ float softsign_exact(float z) {
    return z / (1.0f + fabsf(z));
}
static __device__ __forceinline__ uint32_t smem_u32(const void* p) {
    uint32_t a;
    asm("{ .reg .u64 t; cvta.to.shared.u64 t, %1; cvt.u32.u64 %0, t; }" : "=r"(a) : "l"(p));
    return a;
}
#define CP_ASYNC16(dst_u32, src_gptr) \
    asm volatile("cp.async.cg.shared.global [%0], [%1], 16;" \
                 :: "r"(dst_u32), "l"(src_gptr) : "memory")
#define CP_COMMIT() asm volatile("cp.async.commit_group;" ::: "memory")
#define CP_WAIT0()  asm volatile("cp.async.wait_group 0;" ::: "memory")

// ---------------- prep: U_bias, Z_p/Z_i/Z_d, I0 (all exact fp32) ----------------
__global__ void prep_kernel(const float* __restrict__ U,
                            const float* __restrict__ R_z,
                            const float* __restrict__ b_z,
                            const float* __restrict__ R_0,
                            const float* __restrict__ b_0,
                            const float* __restrict__ R_b) {
    __shared__ float u[K_SZ];
    int b = blockIdx.x;
    for (int k = threadIdx.x; k < K_SZ; k += blockDim.x) u[k] = U[b * K_SZ + k];
    __syncthreads();

    for (int c = threadIdx.x; c < 1536; c += blockDim.x) {
        if (c >= 1280) continue;  // X0 never affects Ys[-1] for T >= 2
        const float* M; int col; int ncol; float bias = 0.0f;
        if (c < 256)       { M = R_b; col = c;        ncol = 256; }
        else if (c < 1024) { M = R_z; col = c - 256;  ncol = 768; bias = b_z[col]; }
        else               { M = R_0; col = c - 1024; ncol = 512; bias = b_0[col]; }
        float acc = bias;
        #pragma unroll 8
        for (int k = 0; k < K_SZ; k++) acc = fmaf(u[k], M[k * ncol + col], acc);

        if (c < 256) {
            g_Ubias[b * UN + c] = acc;
        } else if (c < 1024) {
            int cc = c - 256;
            int un = cc / 3, which = cc % 3;
            if (which == 0)      g_Zp[b * UN + un] = acc;
            else if (which == 1) g_Zi[b * UN + un] = acc;
            else                 g_Zd[b * UN + un] = acc;
        } else {
            g_I[b * UN + (c - 1024)] = acc;    // I0
        }
    }
}

// ---------------- W_i -> bf16 hi/lo split [k][n] ----------------
__global__ void ws_kernel(const float* __restrict__ W_i) {
    int idx = blockIdx.x * blockDim.x + threadIdx.x;
    if (idx >= K_SZ * UN) return;
    int k = idx >> 8, n = idx & 255;
    float w = W_i[idx];
    __nv_bfloat16 hi = __float2bfloat16(w);
    __nv_bfloat16 lo = __float2bfloat16(w - __bfloat162float(hi));
    g_Ws[0][k][n] = hi;
    g_Ws[1][k][n] = lo;
}

// ====== fused-split GEMM: XWi = Xhi@Whi + Xlo@Whi + Xhi@Wlo, X read fp32 once ===
#define BM 128
#define BN 256
#define BK 32
#define A_LD 40    // 32 + 8 pad (80 B/row, 16B-aligned)
#define B_LD 264   // 256 + 8 pad (528 B/row, 16B-aligned)
// per-buffer elements: 2*A + 2*B
#define A_ELE (BM * A_LD)
#define B_ELE (BK * B_LD)
#define BUF_ELE (2 * A_ELE + 2 * B_ELE)          // 27136 bf16
#define GEMM_SMEM (2 * BUF_ELE * 2)              // 108544 bytes

__global__ void __launch_bounds__(512, 1) gemm_kernel(const float* __restrict__ X) {
    using namespace nvcuda;
    extern __shared__ __align__(16) __nv_bfloat16 sm[];

    const int tid = threadIdx.x;
    const int m0  = blockIdx.x * BM;
    const int w   = tid >> 5;
    const int wm  = w >> 2;      // 0..3  (rows of 32)
    const int wn  = w & 3;       // 0..3  (cols of 64)

    const uint32_t smem_base = smem_u32(sm);

    // A-load indexing: 1024 float4 per chunk, 2 per thread
    const int a_row = (tid * 2) >> 3;        // wrong granularity if interleaved; use it-split
    (void)a_row;

    wmma::fragment<wmma::accumulator, 16, 16, 16, float> acc[2][4];
    #pragma unroll
    for (int i = 0; i < 2; i++)
        #pragma unroll
        for (int j = 0; j < 4; j++)
            wmma::fill_fragment(acc[i][j], 0.0f);

    float4 areg[2];

    // ---- staging helpers (inlined manually) ----
    // buffer base offsets (elements)
    //   A_hi: buf*BUF_ELE              A_lo: + A_ELE
    //   B_hi: + 2*A_ELE                B_lo: + 2*A_ELE + B_ELE

    // prologue: load A regs for chunk 0, cp.async B for chunk 0
    {
        #pragma unroll
        for (int it = 0; it < 2; it++) {
            int i = tid + it * 512;              // 0..1023
            int row = i >> 3, c4 = i & 7;
            areg[it] = *reinterpret_cast<const float4*>(
                X + (size_t)(m0 + row) * K_SZ + 0 * BK + c4 * 4);
        }
        #pragma unroll
        for (int it = 0; it < 4; it++) {
            int i = tid + it * 512;              // 0..2047
            int which = i >> 10;
            int j = i & 1023;
            int row = j >> 5, q = j & 31;        // 32 uint4 per row
            const void* src = &g_Ws[which][0 * BK + row][q * 8];
            uint32_t dst = smem_base +
                (2 * A_ELE + which * B_ELE + row * B_LD + q * 8) * 2;
            CP_ASYNC16(dst, (const void*)__cvta_generic_to_global(src));
        }
        CP_COMMIT();
        // convert + store A chunk 0
        #pragma unroll
        for (int it = 0; it < 2; it++) {
            int i = tid + it * 512;
            int row = i >> 3, c4 = i & 7;
            float4 v = areg[it];
            __nv_bfloat162 h01, h23, l01, l23;
            h01.x = __float2bfloat16(v.x); h01.y = __float2bfloat16(v.y);
            h23.x = __float2bfloat16(v.z); h23.y = __float2bfloat16(v.w);
            l01.x = __float2bfloat16(v.x - __bfloat162float(h01.x));
            l01.y = __float2bfloat16(v.y - __bfloat162float(h01.y));
            l23.x = __float2bfloat16(v.z - __bfloat162float(h23.x));
            l23.y = __float2bfloat16(v.w - __bfloat162float(h23.y));
            uint2 hv, lv;
            hv.x = *reinterpret_cast<uint32_t*>(&h01); hv.y = *reinterpret_cast<uint32_t*>(&h23);
            lv.x = *reinterpret_cast<uint32_t*>(&l01); lv.y = *reinterpret_cast<uint32_t*>(&l23);
            *reinterpret_cast<uint2*>(&sm[row * A_LD + c4 * 4])         = hv;
            *reinterpret_cast<uint2*>(&sm[A_ELE + row * A_LD + c4 * 4]) = lv;
        }
        CP_WAIT0();
        __syncthreads();
    }

    #pragma unroll 1
    for (int s = 0; s < K_SZ / BK; s++) {
        const int buf = s & 1;
        __nv_bfloat16* Ahi = sm + buf * BUF_ELE;
        __nv_bfloat16* Alo = Ahi + A_ELE;
        __nv_bfloat16* Bhi = Ahi + 2 * A_ELE;
        __nv_bfloat16* Blo = Bhi + B_ELE;
        const int nbuf = buf ^ 1;

        // start next chunk's loads (A into regs, B via cp.async)
        if (s + 1 < K_SZ / BK) {
            #pragma unroll
            for (int it = 0; it < 2; it++) {
                int i = tid + it * 512;
                int row = i >> 3, c4 = i & 7;
                areg[it] = *reinterpret_cast<const float4*>(
                    X + (size_t)(m0 + row) * K_SZ + (s + 1) * BK + c4 * 4);
            }
            #pragma unroll
            for (int it = 0; it < 4; it++) {
                int i = tid + it * 512;
                int which = i >> 10;
                int j = i & 1023;
                int row = j >> 5, q = j & 31;
                const void* src = &g_Ws[which][(s + 1) * BK + row][q * 8];
                uint32_t dst = smem_base +
                    (nbuf * BUF_ELE + 2 * A_ELE + which * B_ELE + row * B_LD + q * 8) * 2;
                CP_ASYNC16(dst, (const void*)__cvta_generic_to_global(src));
            }
            CP_COMMIT();
        }

        // compute on current buffer (hides next A LDG + B cp.async latency)
        #pragma unroll
        for (int kk = 0; kk < BK; kk += 16) {
            wmma::fragment<wmma::matrix_a, 16, 16, 16, __nv_bfloat16, wmma::row_major> ahi[2];
            wmma::fragment<wmma::matrix_b, 16, 16, 16, __nv_bfloat16, wmma::row_major> bb[4];
            #pragma unroll
            for (int i = 0; i < 2; i++)
                wmma::load_matrix_sync(ahi[i], &Ahi[(wm * 32 + i * 16) * A_LD + kk], A_LD);
            #pragma unroll
            for (int j = 0; j < 4; j++)
                wmma::load_matrix_sync(bb[j], &Bhi[kk * B_LD + wn * 64 + j * 16], B_LD);
            #pragma unroll
            for (int i = 0; i < 2; i++)
                #pragma unroll
                for (int j = 0; j < 4; j++)
                    wmma::mma_sync(acc[i][j], ahi[i], bb[j], acc[i][j]);   // Ahi*Bhi
            {
                wmma::fragment<wmma::matrix_a, 16, 16, 16, __nv_bfloat16, wmma::row_major> alo[2];
                #pragma unroll
                for (int i = 0; i < 2; i++)
                    wmma::load_matrix_sync(alo[i], &Alo[(wm * 32 + i * 16) * A_LD + kk], A_LD);
                #pragma unroll
                for (int i = 0; i < 2; i++)
                    #pragma unroll
                    for (int j = 0; j < 4; j++)
                        wmma::mma_sync(acc[i][j], alo[i], bb[j], acc[i][j]);  // Alo*Bhi
            }
            #pragma unroll
            for (int j = 0; j < 4; j++)
                wmma::load_matrix_sync(bb[j], &Blo[kk * B_LD + wn * 64 + j * 16], B_LD);
            #pragma unroll
            for (int i = 0; i < 2; i++)
                #pragma unroll
                for (int j = 0; j < 4; j++)
                    wmma::mma_sync(acc[i][j], ahi[i], bb[j], acc[i][j]);   // Ahi*Blo
        }

        // finish staging next buffer: convert + store A, drain cp.async
        if (s + 1 < K_SZ / BK) {
            __nv_bfloat16* nAhi = sm + nbuf * BUF_ELE;
            __nv_bfloat16* nAlo = nAhi + A_ELE;
            #pragma unroll
            for (int it = 0; it < 2; it++) {
                int i = tid + it * 512;
                int row = i >> 3, c4 = i & 7;
                float4 v = areg[it];
                __nv_bfloat162 h01, h23, l01, l23;
                h01.x = __float2bfloat16(v.x); h01.y = __float2bfloat16(v.y);
                h23.x = __float2bfloat16(v.z); h23.y = __float2bfloat16(v.w);
                l01.x = __float2bfloat16(v.x - __bfloat162float(h01.x));
                l01.y = __float2bfloat16(v.y - __bfloat162float(h01.y));
                l23.x = __float2bfloat16(v.z - __bfloat162float(h23.x));
                l23.y = __float2bfloat16(v.w - __bfloat162float(h23.y));
                uint2 hv, lv;
                hv.x = *reinterpret_cast<uint32_t*>(&h01); hv.y = *reinterpret_cast<uint32_t*>(&h23);
                lv.x = *reinterpret_cast<uint32_t*>(&l01); lv.y = *reinterpret_cast<uint32_t*>(&l23);
                *reinterpret_cast<uint2*>(&nAhi[row * A_LD + c4 * 4]) = hv;
                *reinterpret_cast<uint2*>(&nAlo[row * A_LD + c4 * 4]) = lv;
            }
            CP_WAIT0();
        }
        __syncthreads();
    }

    #pragma unroll
    for (int i = 0; i < 2; i++)
        #pragma unroll
        for (int j = 0; j < 4; j++)
            wmma::store_matrix_sync(
                &g_XWi[(size_t)(m0 + wm * 32 + i * 16) * UN + wn * 64 + j * 16],
                acc[i][j], UN, wmma::mem_row_major);
}

// ---------------- sequential softsign scan over T ----------------
#define SCAN_D 16
__global__ void scan_kernel() {
    int idx = blockIdx.x * blockDim.x + threadIdx.x;  // 16384 chains
    int b = idx >> 8, u = idx & 255;
    const float* __restrict__ p = g_XWi + (size_t)b * T_SZ * UN + u;
    float I = g_I[idx];

    float buf[SCAN_D];
    #pragma unroll
    for (int d = 0; d < SCAN_D; d++) buf[d] = p[(size_t)d * UN];

    for (int t0 = 0; t0 < T_SZ; t0 += SCAN_D) {
        #pragma unroll
        for (int d = 0; d < SCAN_D; d++) {
            float v = buf[d];
            int tn = t0 + d + SCAN_D;
            if (tn < T_SZ) buf[d] = p[(size_t)tn * UN];
            float z = I + v;
            I = __fdividef(z, 1.0f + fabsf(z));
        }
    }
    g_I[idx] = I;
}

// ---------------- epilogue: P, D (last step only) and Y ----------------
__global__ void epilogue_kernel(const float* __restrict__ X,
                                const float* __restrict__ W_p,
                                const float* __restrict__ W_d,
                                float* __restrict__ out) {
    int b = blockIdx.x;
    int u = threadIdx.x;
    __shared__ float xl[K_SZ];
    __shared__ float dx[K_SZ];
    const float* xlast = X + ((size_t)b * T_SZ + (T_SZ - 1)) * K_SZ;
    const float* xprev = X + ((size_t)b * T_SZ + (T_SZ - 2)) * K_SZ;
    for (int k = u; k < K_SZ; k += blockDim.x) {
        float a = xlast[k];
        xl[k] = a;
        dx[k] = a - xprev[k];
    }
    __syncthreads();

    float pacc = g_Ubias[b * UN + u];
    float dacc = 0.0f;
    #pragma unroll 8
    for (int k = 0; k < K_SZ; k++) {
        pacc = fmaf(xl[k], W_p[k * UN + u], pacc);
        dacc = fmaf(dx[k], W_d[k * UN + u], dacc);
    }
    float P  = softsign_exact(pacc);
    float Dv = softsign_exact(dacc);
    float I  = g_I[b * UN + u];
    out[b * UN + u] = g_Zp[b * UN + u] * P + g_Zi[b * UN + u] * I + g_Zd[b * UN + u] * Dv;
}

// ---------------- launcher ----------------
extern "C" void kernel_launch(void* const* d_in, const int* in_sizes, int n_in,
                              void* d_out, int out_size) {
    const float* U   = (const float*)d_in[0];
    const float* X   = (const float*)d_in[1];
    const float* R_z = (const float*)d_in[2];
    const float* b_z = (const float*)d_in[3];
    const float* R_0 = (const float*)d_in[4];
    const float* b_0 = (const float*)d_in[5];
    const float* R_b = (const float*)d_in[6];
    const float* W_p = (const float*)d_in[7];
    const float* W_i = (const float*)d_in[8];
    const float* W_d = (const float*)d_in[9];
    float* out = (float*)d_out;

    cudaFuncSetAttribute(gemm_kernel,
                         cudaFuncAttributeMaxDynamicSharedMemorySize, GEMM_SMEM);

    prep_kernel<<<B_SZ, 256>>>(U, R_z, b_z, R_0, b_0, R_b);
    ws_kernel<<<(K_SZ * UN + 255) / 256, 256>>>(W_i);
    gemm_kernel<<<M_SZ / BM, 512, GEMM_SMEM>>>(X);
    scan_kernel<<<64, 256>>>();
    epilogue_kernel<<<B_SZ, 256>>>(X, W_p, W_d, out);
}

// round 4
// speedup vs baseline: 1.2841x; 1.0023x over previous
#include <cuda_runtime.h>
#include <cuda_bf16.h>
#include <mma.h>
#include <cstdint>

#define B_SZ 64
#define T_SZ 2048
#define K_SZ 256      // U_dim == X_dim
#define UN   256      // units

// ---------------- device scratch (no runtime allocation allowed) ----------------
__device__ float g_Ubias[B_SZ * UN];
__device__ float g_Zp[B_SZ * UN];
__device__ float g_Zi[B_SZ * UN];
__device__ float g_Zd[B_SZ * UN];
__device__ float g_I[B_SZ * UN];   // I state: prep writes I0, fused writes I_{T-1}

static __device__ __forceinline__ float softsign_exact(float z) {
    return z / (1.0f + fabsf(z));
}

// ---------------- prep: U_bias, Z_p/Z_i/Z_d, I0 (all exact fp32) ----------------
__global__ void prep_kernel(const float* __restrict__ U,
                            const float* __restrict__ R_z,
                            const float* __restrict__ b_z,
                            const float* __restrict__ R_0,
                            const float* __restrict__ b_0,
                            const float* __restrict__ R_b) {
    __shared__ float u[K_SZ];
    int b = blockIdx.x;
    for (int k = threadIdx.x; k < K_SZ; k += blockDim.x) u[k] = U[b * K_SZ + k];
    __syncthreads();

    for (int c = threadIdx.x; c < 1536; c += blockDim.x) {
        if (c >= 1280) continue;  // X0 never affects Ys[-1] for T >= 2
        const float* M; int col; int ncol; float bias = 0.0f;
        if (c < 256)       { M = R_b; col = c;        ncol = 256; }
        else if (c < 1024) { M = R_z; col = c - 256;  ncol = 768; bias = b_z[col]; }
        else               { M = R_0; col = c - 1024; ncol = 512; bias = b_0[col]; }
        float acc = bias;
        #pragma unroll 8
        for (int k = 0; k < K_SZ; k++) acc = fmaf(u[k], M[k * ncol + col], acc);

        if (c < 256) {
            g_Ubias[b * UN + c] = acc;
        } else if (c < 1024) {
            int cc = c - 256;
            int un = cc / 3, which = cc % 3;
            if (which == 0)      g_Zp[b * UN + un] = acc;
            else if (which == 1) g_Zi[b * UN + un] = acc;
            else                 g_Zd[b * UN + un] = acc;
        } else {
            g_I[b * UN + (c - 1024)] = acc;    // I0
        }
    }
}

// =============== fused GEMM + softsign scan (persistent per (b, n-half)) =======
// CTA: b = blockIdx.x>>1, n0 = (blockIdx.x&1)*128. W half resident in smem as
// hi/lo bf16. Streams X[b] in 64-row t-chunks x 64-col k-chunks; 3-term bf16
// split product accumulated in fp32 wmma fragments; per-chunk scan from smem.
#define TM 64
#define TN 128
#define KC 64
#define A_LD 72      // 64 + 8 pad
#define B_LD 136     // 128 + 8 pad
#define O_LD 136

#define OFF_BHI 0
#define OFF_BLO (K_SZ * B_LD * 2)                 // 69632
#define OFF_A   (2 * (K_SZ * B_LD * 2))           // 139264
#define A_HALF  (TM * A_LD * 2)                   // 9216 bytes (one of hi/lo)
#define OFF_OUT (OFF_A + 4 * A_HALF)              // 176128
#define FUSED_SMEM (OFF_OUT + TM * O_LD * 4)      // 210944 bytes

static __device__ __forceinline__ void split4(float4 v, uint2& hv, uint2& lv) {
    __nv_bfloat162 h01, h23, l01, l23;
    h01.x = __float2bfloat16(v.x); h01.y = __float2bfloat16(v.y);
    h23.x = __float2bfloat16(v.z); h23.y = __float2bfloat16(v.w);
    l01.x = __float2bfloat16(v.x - __bfloat162float(h01.x));
    l01.y = __float2bfloat16(v.y - __bfloat162float(h01.y));
    l23.x = __float2bfloat16(v.z - __bfloat162float(h23.x));
    l23.y = __float2bfloat16(v.w - __bfloat162float(h23.y));
    hv.x = *reinterpret_cast<uint32_t*>(&h01);
    hv.y = *reinterpret_cast<uint32_t*>(&h23);
    lv.x = *reinterpret_cast<uint32_t*>(&l01);
    lv.y = *reinterpret_cast<uint32_t*>(&l23);
}

__global__ void __launch_bounds__(512, 1) fused_kernel(const float* __restrict__ X,
                                                       const float* __restrict__ W_i) {
    using namespace nvcuda;
    extern __shared__ __align__(16) char smc[];
    __nv_bfloat16* const Bhi = reinterpret_cast<__nv_bfloat16*>(smc + OFF_BHI);
    __nv_bfloat16* const Blo = reinterpret_cast<__nv_bfloat16*>(smc + OFF_BLO);
    float*         const outs = reinterpret_cast<float*>(smc + OFF_OUT);

    const int tid = threadIdx.x;
    const int wid = tid >> 5;
    const int wm  = wid >> 2;        // 0..3 : t rows of 16
    const int wn  = wid & 3;         // 0..3 : n cols of 32
    const int b   = blockIdx.x >> 1;
    const int n0  = (blockIdx.x & 1) * TN;
    const float* const Xb = X + (size_t)b * T_SZ * K_SZ;

    // ---- stage W half -> resident Bhi/Blo (K-major [k][n], SW-free padded) ----
    #pragma unroll
    for (int it = 0; it < 16; it++) {
        int idx = tid + it * 512;               // 0..8191 float4s
        int row = idx >> 5, c4 = idx & 31;      // 32 float4 per row of 128
        float4 v = *reinterpret_cast<const float4*>(W_i + row * UN + n0 + c4 * 4);
        uint2 hv, lv;
        split4(v, hv, lv);
        *reinterpret_cast<uint2*>(&Bhi[row * B_LD + c4 * 4]) = hv;
        *reinterpret_cast<uint2*>(&Blo[row * B_LD + c4 * 4]) = lv;
    }

    // ---- carry state ----
    float I = 0.0f;
    if (tid < TN) I = g_I[b * UN + n0 + tid];

    wmma::fragment<wmma::accumulator, 16, 16, 16, float> acc[2];
    #pragma unroll
    for (int j = 0; j < 2; j++) wmma::fill_fragment(acc[j], 0.0f);

    // X staging regs: 64 t x 64 k fp32 per kc = 1024 float4 / 512 thr = 2 each
    float4 xr[2];
    const int xrow0 = (tid + 0 * 512) >> 4, xc40 = (tid + 0 * 512) & 15;
    const int xrow1 = (tid + 1 * 512) >> 4, xc41 = (tid + 1 * 512) & 15;

    // prologue: chunk 0, kc 0
    xr[0] = *reinterpret_cast<const float4*>(Xb + (size_t)xrow0 * K_SZ + xc40 * 4);
    xr[1] = *reinterpret_cast<const float4*>(Xb + (size_t)xrow1 * K_SZ + xc41 * 4);
    __syncthreads();   // W resident before first GEMM

    #pragma unroll 1
    for (int c = 0; c < T_SZ / TM; c++) {
        const int t0 = c * TM;
        #pragma unroll
        for (int kc = 0; kc < K_SZ / KC; kc++) {
            const int buf = kc & 1;
            __nv_bfloat16* const Ah = reinterpret_cast<__nv_bfloat16*>(
                smc + OFF_A + buf * 2 * A_HALF);
            __nv_bfloat16* const Al = reinterpret_cast<__nv_bfloat16*>(
                smc + OFF_A + buf * 2 * A_HALF + A_HALF);

            // convert + STS current kc
            {
                uint2 hv, lv;
                split4(xr[0], hv, lv);
                *reinterpret_cast<uint2*>(&Ah[xrow0 * A_LD + xc40 * 4]) = hv;
                *reinterpret_cast<uint2*>(&Al[xrow0 * A_LD + xc40 * 4]) = lv;
                split4(xr[1], hv, lv);
                *reinterpret_cast<uint2*>(&Ah[xrow1 * A_LD + xc41 * 4]) = hv;
                *reinterpret_cast<uint2*>(&Al[xrow1 * A_LD + xc41 * 4]) = lv;
            }
            // prefetch next kc (or next chunk's kc=0)
            {
                int nt0, nkc;
                bool more = true;
                if (kc + 1 < K_SZ / KC)      { nt0 = t0;      nkc = kc + 1; }
                else if (c + 1 < T_SZ / TM)  { nt0 = t0 + TM; nkc = 0; }
                else more = false;
                if (more) {
                    const float* src = Xb + (size_t)nt0 * K_SZ + nkc * KC;
                    xr[0] = *reinterpret_cast<const float4*>(src + (size_t)xrow0 * K_SZ + xc40 * 4);
                    xr[1] = *reinterpret_cast<const float4*>(src + (size_t)xrow1 * K_SZ + xc41 * 4);
                }
            }
            __syncthreads();

            // GEMM on staged buffer (B resident)
            #pragma unroll
            for (int kk = 0; kk < KC / 16; kk++) {
                wmma::fragment<wmma::matrix_a, 16, 16, 16, __nv_bfloat16, wmma::row_major> ah, al;
                wmma::load_matrix_sync(ah, &Ah[(wm * 16) * A_LD + kk * 16], A_LD);
                wmma::load_matrix_sync(al, &Al[(wm * 16) * A_LD + kk * 16], A_LD);
                const int krow = kc * KC + kk * 16;
                #pragma unroll
                for (int j = 0; j < 2; j++) {
                    wmma::fragment<wmma::matrix_b, 16, 16, 16, __nv_bfloat16, wmma::row_major> bh, bl;
                    wmma::load_matrix_sync(bh, &Bhi[krow * B_LD + wn * 32 + j * 16], B_LD);
                    wmma::load_matrix_sync(bl, &Blo[krow * B_LD + wn * 32 + j * 16], B_LD);
                    wmma::mma_sync(acc[j], ah, bh, acc[j]);   // Xhi*Whi
                    wmma::mma_sync(acc[j], al, bh, acc[j]);   // Xlo*Whi
                    wmma::mma_sync(acc[j], ah, bl, acc[j]);   // Xhi*Wlo
                }
            }
            // NOTE: kc-loop sync (top of next iter) separates buffer reuse
        }

        // store chunk result to smem, reset acc
        #pragma unroll
        for (int j = 0; j < 2; j++) {
            wmma::store_matrix_sync(&outs[(wm * 16) * O_LD + wn * 32 + j * 16],
                                    acc[j], O_LD, wmma::mem_row_major);
            wmma::fill_fragment(acc[j], 0.0f);
        }
        __syncthreads();   // outs visible to scan warps

        // serial softsign scan of 64 steps (threads 0..127 own one u each)
        if (tid < TN) {
            float v  = outs[tid];
            float vn = outs[O_LD + tid];
            #pragma unroll 8
            for (int t = 0; t < TM; t++) {
                float z = I + v;
                v = vn;
                if (t + 2 < TM) vn = outs[(t + 2) * O_LD + tid];
                I = __fdividef(z, 1.0f + fabsf(z));
            }
        }
        // no sync needed here: next chunk's first kc-sync orders scan vs A reuse;
        // outs is only rewritten after that chunk's GEMM completes (post-GEMM sync).
    }

    if (tid < TN) g_I[b * UN + n0 + tid] = I;
}

// ---------------- epilogue: P, D (last step only) and Y ----------------
__global__ void epilogue_kernel(const float* __restrict__ X,
                                const float* __restrict__ W_p,
                                const float* __restrict__ W_d,
                                float* __restrict__ out) {
    int b = blockIdx.x;
    int u = threadIdx.x;
    __shared__ float xl[K_SZ];
    __shared__ float dx[K_SZ];
    const float* xlast = X + ((size_t)b * T_SZ + (T_SZ - 1)) * K_SZ;
    const float* xprev = X + ((size_t)b * T_SZ + (T_SZ - 2)) * K_SZ;
    for (int k = u; k < K_SZ; k += blockDim.x) {
        float a = xlast[k];
        xl[k] = a;
        dx[k] = a - xprev[k];
    }
    __syncthreads();

    float pacc = g_Ubias[b * UN + u];
    float dacc = 0.0f;
    #pragma unroll 8
    for (int k = 0; k < K_SZ; k++) {
        pacc = fmaf(xl[k], W_p[k * UN + u], pacc);
        dacc = fmaf(dx[k], W_d[k * UN + u], dacc);
    }
    float P  = softsign_exact(pacc);
    float Dv = softsign_exact(dacc);
    float I  = g_I[b * UN + u];
    out[b * UN + u] = g_Zp[b * UN + u] * P + g_Zi[b * UN + u] * I + g_Zd[b * UN + u] * Dv;
}

// ---------------- launcher ----------------
extern "C" void kernel_launch(void* const* d_in, const int* in_sizes, int n_in,
                              void* d_out, int out_size) {
    const float* U   = (const float*)d_in[0];
    const float* X   = (const float*)d_in[1];
    const float* R_z = (const float*)d_in[2];
    const float* b_z = (const float*)d_in[3];
    const float* R_0 = (const float*)d_in[4];
    const float* b_0 = (const float*)d_in[5];
    const float* R_b = (const float*)d_in[6];
    const float* W_p = (const float*)d_in[7];
    const float* W_i = (const float*)d_in[8];
    const float* W_d = (const float*)d_in[9];
    float* out = (float*)d_out;

    cudaFuncSetAttribute(fused_kernel,
                         cudaFuncAttributeMaxDynamicSharedMemorySize, FUSED_SMEM);

    prep_kernel<<<B_SZ, 256>>>(U, R_z, b_z, R_0, b_0, R_b);
    fused_kernel<<<2 * B_SZ, 512, FUSED_SMEM>>>(X, W_i);
    epilogue_kernel<<<B_SZ, 256>>>(X, W_p, W_d, out);
}

// round 6
// speedup vs baseline: 1.9736x; 1.5369x over previous
#include <cuda_runtime.h>
#include <cuda_bf16.h>
#include <mma.h>
#include <cstdint>

#define B_SZ 64
#define T_SZ 2048
#define K_SZ 256      // U_dim == X_dim
#define UN   256      // units

// ---------------- device scratch (no runtime allocation allowed) ----------------
__device__ float g_Ubias[B_SZ * UN];
__device__ float g_Zp[B_SZ * UN];
__device__ float g_Zi[B_SZ * UN];
__device__ float g_Zd[B_SZ * UN];
__device__ float g_I[B_SZ * UN];   // I state: prep writes I0, fused writes I_{T-1}

static __device__ __forceinline__ float softsign_exact(float z) {
    return z / (1.0f + fabsf(z));
}

#define BAR_SYNC(id, cnt)   asm volatile("bar.sync %0, %1;"   :: "r"(id), "r"(cnt) : "memory")
#define BAR_ARRIVE(id, cnt) asm volatile("bar.arrive %0, %1;" :: "r"(id), "r"(cnt) : "memory")

// ---------------- prep: U_bias, Z_p/Z_i/Z_d, I0 (k-split, 1280 blocks) ---------
__global__ void prep_kernel(const float* __restrict__ U,
                            const float* __restrict__ R_z,
                            const float* __restrict__ b_z,
                            const float* __restrict__ R_0,
                            const float* __restrict__ b_0,
                            const float* __restrict__ R_b) {
    __shared__ float u[K_SZ];
    __shared__ float part[4][72];
    const int b  = blockIdx.x;
    const int cl = threadIdx.x & 63;
    const int ks = threadIdx.x >> 6;
    const int c  = blockIdx.y * 64 + cl;   // 0..1279

    if (threadIdx.x < K_SZ) u[threadIdx.x] = U[b * K_SZ + threadIdx.x];
    __syncthreads();

    const float* M; int col; int ncol;
    if (c < 256)       { M = R_b; col = c;        ncol = 256; }
    else if (c < 1024) { M = R_z; col = c - 256;  ncol = 768; }
    else               { M = R_0; col = c - 1024; ncol = 512; }

    float acc = 0.0f;
    const float* Mp = M + (size_t)(ks * 64) * ncol + col;
    #pragma unroll 16
    for (int k = 0; k < 64; k++) acc = fmaf(u[ks * 64 + k], Mp[(size_t)k * ncol], acc);
    part[ks][cl] = acc;
    __syncthreads();

    if (ks == 0) {
        float tot = part[0][cl] + part[1][cl] + part[2][cl] + part[3][cl];
        if (c < 256) {
            g_Ubias[b * UN + c] = tot;
        } else if (c < 1024) {
            int cc = c - 256;
            tot += b_z[cc];
            int un = cc / 3, which = cc % 3;
            if (which == 0)      g_Zp[b * UN + un] = tot;
            else if (which == 1) g_Zi[b * UN + un] = tot;
            else                 g_Zd[b * UN + un] = tot;
        } else {
            g_I[b * UN + (c - 1024)] = tot + b_0[c - 1024];   // I0
        }
    }
}

// =============== fused GEMM + softsign scan, warp-specialized ==================
// 128 CTAs: b = blockIdx.x>>1, n0 = (blockIdx.x&1)*128. blockDim=384:
//   warps 0-7  (tid<256): GEMM producers, 32x32 warp tiles over 64x128 chunk
//   warps 8-11 (tid>=256): scan consumers (128 u-chains)
// Per-buffer barrier pairs (overrun-proof): READY[buf]=2+buf, FREE[buf]=4+buf.
// Producer syncs FREE[buf] before re-arriving READY[buf] -> each barrier sees
// exactly one arrive-phase per sync-phase.
#define TM 64
#define TN 128
#define KC 32
#define A_LD 40      // 32 + 8 pad
#define B_LD 136     // 128 + 8 pad
#define O_LD 136

#define A_HALF  (TM * A_LD * 2)                   // 5120 B (one of hi/lo)
#define OFF_BHI 0
#define OFF_BLO (K_SZ * B_LD * 2)                 // 69632
#define OFF_A   (2 * (K_SZ * B_LD * 2))           // 139264
#define OFF_OUT (OFF_A + 4 * A_HALF)              // 159744
#define OUT_ELE (TM * O_LD)                       // floats per buffer
#define FUSED_SMEM (OFF_OUT + 2 * OUT_ELE * 4)    // 229376 bytes

#define NCHUNK (T_SZ / TM)        // 32
#define NKC    (K_SZ / KC)        // 8

static __device__ __forceinline__ void split4(float4 v, uint2& hv, uint2& lv) {
    __nv_bfloat162 h01, h23, l01, l23;
    h01.x = __float2bfloat16(v.x); h01.y = __float2bfloat16(v.y);
    h23.x = __float2bfloat16(v.z); h23.y = __float2bfloat16(v.w);
    l01.x = __float2bfloat16(v.x - __bfloat162float(h01.x));
    l01.y = __float2bfloat16(v.y - __bfloat162float(h01.y));
    l23.x = __float2bfloat16(v.z - __bfloat162float(h23.x));
    l23.y = __float2bfloat16(v.w - __bfloat162float(h23.y));
    hv.x = *reinterpret_cast<uint32_t*>(&h01);
    hv.y = *reinterpret_cast<uint32_t*>(&h23);
    lv.x = *reinterpret_cast<uint32_t*>(&l01);
    lv.y = *reinterpret_cast<uint32_t*>(&l23);
}

__global__ void __launch_bounds__(384, 1) fused_kernel(const float* __restrict__ X,
                                                       const float* __restrict__ W_i) {
    using namespace nvcuda;
    extern __shared__ __align__(16) char smc[];
    __nv_bfloat16* const Bhi  = reinterpret_cast<__nv_bfloat16*>(smc + OFF_BHI);
    __nv_bfloat16* const Blo  = reinterpret_cast<__nv_bfloat16*>(smc + OFF_BLO);
    float*         const outs = reinterpret_cast<float*>(smc + OFF_OUT);

    const int tid = threadIdx.x;
    const int b   = blockIdx.x >> 1;
    const int n0  = (blockIdx.x & 1) * TN;
    const float* const Xb = X + (size_t)b * T_SZ * K_SZ;

    // ---- stage resident W half as hi/lo bf16 (all 384 threads) ----
    for (int idx = tid; idx < K_SZ * (TN / 4); idx += 384) {   // 8192 float4
        int row = idx >> 5, c4 = idx & 31;
        float4 v = *reinterpret_cast<const float4*>(W_i + (size_t)row * UN + n0 + c4 * 4);
        uint2 hv, lv;
        split4(v, hv, lv);
        *reinterpret_cast<uint2*>(&Bhi[row * B_LD + c4 * 4]) = hv;
        *reinterpret_cast<uint2*>(&Blo[row * B_LD + c4 * 4]) = lv;
    }
    __syncthreads();

    if (tid < 256) {
        // ======================= GEMM producer group =======================
        const int wid = tid >> 5;
        const int wm  = wid >> 2;        // 0..1 : rows of 32
        const int wn  = wid & 3;         // 0..3 : cols of 32

        wmma::fragment<wmma::accumulator, 16, 16, 16, float> acc[2][2];
        #pragma unroll
        for (int i = 0; i < 2; i++)
            #pragma unroll
            for (int j = 0; j < 2; j++) wmma::fill_fragment(acc[i][j], 0.0f);

        // X staging: 512 float4 per kc / 256 thr = 2 each
        float4 xr[2];
        const int xrow0 = tid >> 3,         xc40 = tid & 7;
        const int xrow1 = (tid + 256) >> 3, xc41 = (tid + 256) & 7;

        xr[0] = *reinterpret_cast<const float4*>(Xb + (size_t)xrow0 * K_SZ + xc40 * 4);
        xr[1] = *reinterpret_cast<const float4*>(Xb + (size_t)xrow1 * K_SZ + xc41 * 4);

        #pragma unroll 1
        for (int step = 0; step < NCHUNK * NKC; step++) {
            const int c    = step >> 3;
            const int kc   = step & 7;
            const int abuf = step & 1;
            __nv_bfloat16* const Ah = reinterpret_cast<__nv_bfloat16*>(
                smc + OFF_A + abuf * 2 * A_HALF);
            __nv_bfloat16* const Al = reinterpret_cast<__nv_bfloat16*>(
                smc + OFF_A + abuf * 2 * A_HALF + A_HALF);

            // convert + STS this kc
            {
                uint2 hv, lv;
                split4(xr[0], hv, lv);
                *reinterpret_cast<uint2*>(&Ah[xrow0 * A_LD + xc40 * 4]) = hv;
                *reinterpret_cast<uint2*>(&Al[xrow0 * A_LD + xc40 * 4]) = lv;
                split4(xr[1], hv, lv);
                *reinterpret_cast<uint2*>(&Ah[xrow1 * A_LD + xc41 * 4]) = hv;
                *reinterpret_cast<uint2*>(&Al[xrow1 * A_LD + xc41 * 4]) = lv;
            }
            // prefetch step+1 into regs
            if (step + 1 < NCHUNK * NKC) {
                const int nc  = (step + 1) >> 3;
                const int nkc = (step + 1) & 7;
                const float* src = Xb + (size_t)(nc * TM) * K_SZ + nkc * KC;
                xr[0] = *reinterpret_cast<const float4*>(src + (size_t)xrow0 * K_SZ + xc40 * 4);
                xr[1] = *reinterpret_cast<const float4*>(src + (size_t)xrow1 * K_SZ + xc41 * 4);
            }
            BAR_SYNC(1, 256);   // staging visible; also fences A buffer reuse

            #pragma unroll
            for (int kk = 0; kk < KC; kk += 16) {
                const int krow = kc * KC + kk;
                wmma::fragment<wmma::matrix_a, 16, 16, 16, __nv_bfloat16, wmma::row_major> ah[2], al[2];
                wmma::fragment<wmma::matrix_b, 16, 16, 16, __nv_bfloat16, wmma::row_major> bh[2], bl[2];
                #pragma unroll
                for (int i = 0; i < 2; i++) {
                    wmma::load_matrix_sync(ah[i], &Ah[(wm * 32 + i * 16) * A_LD + kk], A_LD);
                    wmma::load_matrix_sync(al[i], &Al[(wm * 32 + i * 16) * A_LD + kk], A_LD);
                }
                #pragma unroll
                for (int j = 0; j < 2; j++) {
                    wmma::load_matrix_sync(bh[j], &Bhi[krow * B_LD + wn * 32 + j * 16], B_LD);
                    wmma::load_matrix_sync(bl[j], &Blo[krow * B_LD + wn * 32 + j * 16], B_LD);
                }
                #pragma unroll
                for (int i = 0; i < 2; i++)
                    #pragma unroll
                    for (int j = 0; j < 2; j++) {
                        wmma::mma_sync(acc[i][j], ah[i], bh[j], acc[i][j]);   // Xhi*Whi
                        wmma::mma_sync(acc[i][j], al[i], bh[j], acc[i][j]);   // Xlo*Whi
                        wmma::mma_sync(acc[i][j], ah[i], bl[j], acc[i][j]);   // Xhi*Wlo
                    }
            }

            if (kc == 7) {
                const int ob_buf = c & 1;
                // wait until scan of chunk c-2 released this buffer
                if (c >= 2) BAR_SYNC(4 + ob_buf, 384);      // FREE[buf]
                float* ob = outs + ob_buf * OUT_ELE;
                #pragma unroll
                for (int i = 0; i < 2; i++)
                    #pragma unroll
                    for (int j = 0; j < 2; j++) {
                        wmma::store_matrix_sync(&ob[(wm * 32 + i * 16) * O_LD + wn * 32 + j * 16],
                                                acc[i][j], O_LD, wmma::mem_row_major);
                        wmma::fill_fragment(acc[i][j], 0.0f);
                    }
                BAR_ARRIVE(2 + ob_buf, 384);                // READY[buf]
            }
        }
    } else {
        // ======================= scan consumer group =======================
        const int u = tid - 256;          // 0..127
        float I = g_I[b * UN + n0 + u];

        #pragma unroll 1
        for (int c = 0; c < NCHUNK; c++) {
            const int ob_buf = c & 1;
            BAR_SYNC(2 + ob_buf, 384);                      // READY[buf]
            const float* ob = outs + ob_buf * OUT_ELE;
            float v  = ob[u];
            float vn = ob[O_LD + u];
            #pragma unroll 8
            for (int t = 0; t < TM; t++) {
                float z = I + v;
                v = vn;
                if (t + 2 < TM) vn = ob[(t + 2) * O_LD + u];
                I = __fdividef(z, 1.0f + fabsf(z));
            }
            BAR_ARRIVE(4 + ob_buf, 384);                    // FREE[buf]
        }
        g_I[b * UN + n0 + u] = I;
    }
}

// ---------------- epilogue: P, D (last step only) and Y (k-split) --------------
__global__ void epilogue_kernel(const float* __restrict__ X,
                                const float* __restrict__ W_p,
                                const float* __restrict__ W_d,
                                float* __restrict__ out) {
    __shared__ float xl[K_SZ];
    __shared__ float dx[K_SZ];
    __shared__ float pP[4][72];
    __shared__ float pD[4][72];
    const int b  = blockIdx.x;
    const int cl = threadIdx.x & 63;
    const int ks = threadIdx.x >> 6;
    const int u  = blockIdx.y * 64 + cl;

    const float* xlast = X + ((size_t)b * T_SZ + (T_SZ - 1)) * K_SZ;
    const float* xprev = X + ((size_t)b * T_SZ + (T_SZ - 2)) * K_SZ;
    if (threadIdx.x < K_SZ) {
        float a = xlast[threadIdx.x];
        xl[threadIdx.x] = a;
        dx[threadIdx.x] = a - xprev[threadIdx.x];
    }
    __syncthreads();

    float pacc = 0.0f, dacc = 0.0f;
    const float* Wpp = W_p + (size_t)(ks * 64) * UN + u;
    const float* Wdp = W_d + (size_t)(ks * 64) * UN + u;
    #pragma unroll 16
    for (int k = 0; k < 64; k++) {
        pacc = fmaf(xl[ks * 64 + k], Wpp[(size_t)k * UN], pacc);
        dacc = fmaf(dx[ks * 64 + k], Wdp[(size_t)k * UN], dacc);
    }
    pP[ks][cl] = pacc;
    pD[ks][cl] = dacc;
    __syncthreads();

    if (ks == 0) {
        float pt = pP[0][cl] + pP[1][cl] + pP[2][cl] + pP[3][cl] + g_Ubias[b * UN + u];
        float dt = pD[0][cl] + pD[1][cl] + pD[2][cl] + pD[3][cl];
        float P  = softsign_exact(pt);
        float Dv = softsign_exact(dt);
        float I  = g_I[b * UN + u];
        out[b * UN + u] = g_Zp[b * UN + u] * P + g_Zi[b * UN + u] * I + g_Zd[b * UN + u] * Dv;
    }
}

// ---------------- launcher ----------------
extern "C" void kernel_launch(void* const* d_in, const int* in_sizes, int n_in,
                              void* d_out, int out_size) {
    const float* U   = (const float*)d_in[0];
    const float* X   = (const float*)d_in[1];
    const float* R_z = (const float*)d_in[2];
    const float* b_z = (const float*)d_in[3];
    const float* R_0 = (const float*)d_in[4];
    const float* b_0 = (const float*)d_in[5];
    const float* R_b = (const float*)d_in[6];
    const float* W_p = (const float*)d_in[7];
    const float* W_i = (const float*)d_in[8];
    const float* W_d = (const float*)d_in[9];
    float* out = (float*)d_out;

    cudaFuncSetAttribute(fused_kernel,
                         cudaFuncAttributeMaxDynamicSharedMemorySize, FUSED_SMEM);

    prep_kernel<<<dim3(B_SZ, 20), 256>>>(U, R_z, b_z, R_0, b_0, R_b);
    fused_kernel<<<2 * B_SZ, 384, FUSED_SMEM>>>(X, W_i);
    epilogue_kernel<<<dim3(B_SZ, 4), 256>>>(X, W_p, W_d, out);
}

// round 8
// speedup vs baseline: 1.9760x; 1.0012x over previous
#include <cuda_runtime.h>
#include <cuda_bf16.h>
#include <mma.h>
#include <cstdint>

#define B_SZ 64
#define T_SZ 2048
#define K_SZ 256      // U_dim == X_dim
#define UN   256      // units

// ---------------- device scratch ----------------
__device__ float g_I[B_SZ * UN];   // final I_{T-1} written by fused kernel

static __device__ __forceinline__ float softsign_exact(float z) {
    return z / (1.0f + fabsf(z));
}

#define BAR_SYNC(id, cnt)   asm volatile("bar.sync %0, %1;"   :: "r"(id), "r"(cnt) : "memory")
#define BAR_ARRIVE(id, cnt) asm volatile("bar.arrive %0, %1;" :: "r"(id), "r"(cnt) : "memory")

// =============== fused GEMM + softsign scan, fully role-specialized ============
// 128 CTAs: b = blockIdx.x>>1, n0 = (blockIdx.x&1)*128. blockDim=384:
//   tid [0,256)   : GEMM warps, pure LDSM+HMMA (32x32 warp tiles)
//   tid [256,320) : A staging warps (LDG X fp32 -> hi/lo bf16 split -> STS)
//   tid [320,384) : scan warps (2 interleaved u-chains per thread) + I0 compute
// Barriers (all count 320 = 10 warps, one arrive-phase per sync-phase):
//   OUT_READY[buf]=2+buf (GEMM arrive, scan sync), OUT_FREE[buf]=4+buf (scan
//   arrive, GEMM sync), A_READY[buf]=6+buf (staging arrive, GEMM sync),
//   A_FREE[buf]=8+buf (GEMM arrive, staging sync).
#define TM 64
#define TN 128
#define KC 32
#define A_LD 40      // 32 + 8 pad
#define B_LD 136     // 128 + 8 pad
#define O_LD 136

#define A_HALF  (TM * A_LD * 2)                   // 5120 B (one of hi/lo)
#define OFF_BHI 0
#define OFF_BLO (K_SZ * B_LD * 2)                 // 69632
#define OFF_A   (2 * (K_SZ * B_LD * 2))           // 139264
#define OFF_OUT (OFF_A + 4 * A_HALF)              // 159744
#define OUT_ELE (TM * O_LD)                       // floats per buffer
#define FUSED_SMEM (OFF_OUT + 2 * OUT_ELE * 4)    // 229376 bytes

#define NCHUNK (T_SZ / TM)        // 32
#define NKC    (K_SZ / KC)        // 8
#define NSTEP  (NCHUNK * NKC)     // 256

static __device__ __forceinline__ void split4(float4 v, uint2& hv, uint2& lv) {
    __nv_bfloat162 h01, h23, l01, l23;
    h01.x = __float2bfloat16(v.x); h01.y = __float2bfloat16(v.y);
    h23.x = __float2bfloat16(v.z); h23.y = __float2bfloat16(v.w);
    l01.x = __float2bfloat16(v.x - __bfloat162float(h01.x));
    l01.y = __float2bfloat16(v.y - __bfloat162float(h01.y));
    l23.x = __float2bfloat16(v.z - __bfloat162float(h23.x));
    l23.y = __float2bfloat16(v.w - __bfloat162float(h23.y));
    hv.x = *reinterpret_cast<uint32_t*>(&h01);
    hv.y = *reinterpret_cast<uint32_t*>(&h23);
    lv.x = *reinterpret_cast<uint32_t*>(&l01);
    lv.y = *reinterpret_cast<uint32_t*>(&l23);
}

__global__ void __launch_bounds__(384, 1) fused_kernel(const float* __restrict__ U,
                                                       const float* __restrict__ X,
                                                       const float* __restrict__ W_i,
                                                       const float* __restrict__ R_0,
                                                       const float* __restrict__ b_0) {
    using namespace nvcuda;
    extern __shared__ __align__(16) char smc[];
    __nv_bfloat16* const Bhi  = reinterpret_cast<__nv_bfloat16*>(smc + OFF_BHI);
    __nv_bfloat16* const Blo  = reinterpret_cast<__nv_bfloat16*>(smc + OFF_BLO);
    float*         const outs = reinterpret_cast<float*>(smc + OFF_OUT);

    const int tid = threadIdx.x;
    const int b   = blockIdx.x >> 1;
    const int n0  = (blockIdx.x & 1) * TN;
    const float* const Xb = X + (size_t)b * T_SZ * K_SZ;

    // ---- stage resident W half as hi/lo bf16 (warps 0-9; scan warps skip) ----
    if (tid < 320) {
        for (int idx = tid; idx < K_SZ * (TN / 4); idx += 320) {   // 8192 float4
            int row = idx >> 5, c4 = idx & 31;
            float4 v = *reinterpret_cast<const float4*>(W_i + (size_t)row * UN + n0 + c4 * 4);
            uint2 hv, lv;
            split4(v, hv, lv);
            *reinterpret_cast<uint2*>(&Bhi[row * B_LD + c4 * 4]) = hv;
            *reinterpret_cast<uint2*>(&Blo[row * B_LD + c4 * 4]) = lv;
        }
    }
    __syncthreads();

    if (tid < 256) {
        // ======================= GEMM warps (pure compute) =======================
        const int wid = tid >> 5;
        const int wm  = wid >> 2;        // 0..1 : rows of 32
        const int wn  = wid & 3;         // 0..3 : cols of 32

        wmma::fragment<wmma::accumulator, 16, 16, 16, float> acc[2][2];
        #pragma unroll
        for (int i = 0; i < 2; i++)
            #pragma unroll
            for (int j = 0; j < 2; j++) wmma::fill_fragment(acc[i][j], 0.0f);

        #pragma unroll 1
        for (int step = 0; step < NSTEP; step++) {
            const int c    = step >> 3;
            const int kc   = step & 7;
            const int abuf = step & 1;
            __nv_bfloat16* const Ah = reinterpret_cast<__nv_bfloat16*>(
                smc + OFF_A + abuf * 2 * A_HALF);
            __nv_bfloat16* const Al = reinterpret_cast<__nv_bfloat16*>(
                smc + OFF_A + abuf * 2 * A_HALF + A_HALF);

            BAR_SYNC(6 + abuf, 320);     // A_READY[abuf]

            #pragma unroll
            for (int kk = 0; kk < KC; kk += 16) {
                const int krow = kc * KC + kk;
                wmma::fragment<wmma::matrix_a, 16, 16, 16, __nv_bfloat16, wmma::row_major> ah[2], al[2];
                wmma::fragment<wmma::matrix_b, 16, 16, 16, __nv_bfloat16, wmma::row_major> bh[2], bl[2];
                #pragma unroll
                for (int i = 0; i < 2; i++) {
                    wmma::load_matrix_sync(ah[i], &Ah[(wm * 32 + i * 16) * A_LD + kk], A_LD);
                    wmma::load_matrix_sync(al[i], &Al[(wm * 32 + i * 16) * A_LD + kk], A_LD);
                }
                #pragma unroll
                for (int j = 0; j < 2; j++) {
                    wmma::load_matrix_sync(bh[j], &Bhi[krow * B_LD + wn * 32 + j * 16], B_LD);
                    wmma::load_matrix_sync(bl[j], &Blo[krow * B_LD + wn * 32 + j * 16], B_LD);
                }
                #pragma unroll
                for (int i = 0; i < 2; i++)
                    #pragma unroll
                    for (int j = 0; j < 2; j++) {
                        wmma::mma_sync(acc[i][j], ah[i], bh[j], acc[i][j]);   // Xhi*Whi
                        wmma::mma_sync(acc[i][j], al[i], bh[j], acc[i][j]);   // Xlo*Whi
                        wmma::mma_sync(acc[i][j], ah[i], bl[j], acc[i][j]);   // Xhi*Wlo
                    }
            }
            BAR_ARRIVE(8 + abuf, 320);   // A_FREE[abuf]

            if (kc == 7) {
                const int ob_buf = c & 1;
                if (c >= 2) BAR_SYNC(4 + ob_buf, 320);      // OUT_FREE[buf]
                float* ob = outs + ob_buf * OUT_ELE;
                #pragma unroll
                for (int i = 0; i < 2; i++)
                    #pragma unroll
                    for (int j = 0; j < 2; j++) {
                        wmma::store_matrix_sync(&ob[(wm * 32 + i * 16) * O_LD + wn * 32 + j * 16],
                                                acc[i][j], O_LD, wmma::mem_row_major);
                        wmma::fill_fragment(acc[i][j], 0.0f);
                    }
                BAR_ARRIVE(2 + ob_buf, 320);                // OUT_READY[buf]
            }
        }
    } else if (tid < 320) {
        // ======================= A staging warps =======================
        const int st = tid - 256;        // 0..63
        // per step: 64 rows x 8 float4 (32 floats/row). i = r*64+st:
        //   row = i>>3, c4 = i&7 (8-lane groups coalesce 128B rows)
        float4 xr[8];
        int rowv[8], c4v[8];
        #pragma unroll
        for (int r = 0; r < 8; r++) {
            int i = r * 64 + st;
            rowv[r] = i >> 3;
            c4v[r]  = i & 7;
        }
        // prologue: load step 0
        #pragma unroll
        for (int r = 0; r < 8; r++)
            xr[r] = *reinterpret_cast<const float4*>(
                Xb + (size_t)rowv[r] * K_SZ + c4v[r] * 4);

        #pragma unroll 1
        for (int step = 0; step < NSTEP; step++) {
            const int abuf = step & 1;
            __nv_bfloat16* const Ah = reinterpret_cast<__nv_bfloat16*>(
                smc + OFF_A + abuf * 2 * A_HALF);
            __nv_bfloat16* const Al = reinterpret_cast<__nv_bfloat16*>(
                smc + OFF_A + abuf * 2 * A_HALF + A_HALF);

            if (step >= 2) BAR_SYNC(8 + abuf, 320);   // A_FREE[abuf]
            #pragma unroll
            for (int r = 0; r < 8; r++) {
                uint2 hv, lv;
                split4(xr[r], hv, lv);
                *reinterpret_cast<uint2*>(&Ah[rowv[r] * A_LD + c4v[r] * 4]) = hv;
                *reinterpret_cast<uint2*>(&Al[rowv[r] * A_LD + c4v[r] * 4]) = lv;
            }
            BAR_ARRIVE(6 + abuf, 320);                // A_READY[abuf]

            if (step + 1 < NSTEP) {
                const int nc  = (step + 1) >> 3;
                const int nkc = (step + 1) & 7;
                const float* src = Xb + (size_t)(nc * TM) * K_SZ + nkc * KC;
                #pragma unroll
                for (int r = 0; r < 8; r++)
                    xr[r] = *reinterpret_cast<const float4*>(
                        src + (size_t)rowv[r] * K_SZ + c4v[r] * 4);
            }
        }
    } else {
        // ======================= scan warps =======================
        const int u0 = (tid - 320) * 2;   // 0,2,..,126

        // I0 = U@R_0[:, n0+u] + b_0[n0+u]  (overlapped with W staging + GEMM c0)
        float Ia = b_0[n0 + u0];
        float Ib = b_0[n0 + u0 + 1];
        {
            const float* R0c = R_0 + n0 + u0;       // R_0 is [K_SZ][512]
            const float* Ub  = U + (size_t)b * K_SZ;
            #pragma unroll 8
            for (int k = 0; k < K_SZ; k++) {
                float uv = Ub[k];
                Ia = fmaf(uv, R0c[(size_t)k * 512],     Ia);
                Ib = fmaf(uv, R0c[(size_t)k * 512 + 1], Ib);
            }
        }

        #pragma unroll 1
        for (int c = 0; c < NCHUNK; c++) {
            const int ob_buf = c & 1;
            BAR_SYNC(2 + ob_buf, 320);                      // OUT_READY[buf]
            const float* ob = outs + ob_buf * OUT_ELE;
            const float2* obp = reinterpret_cast<const float2*>(ob) + (u0 >> 1);
            float2 v  = obp[0];
            float2 vn = obp[O_LD / 2];
            #pragma unroll 8
            for (int t = 0; t < TM; t++) {
                float za = Ia + v.x;
                float zb = Ib + v.y;
                v = vn;
                if (t + 2 < TM) vn = obp[(size_t)(t + 2) * (O_LD / 2)];
                Ia = __fdividef(za, 1.0f + fabsf(za));
                Ib = __fdividef(zb, 1.0f + fabsf(zb));
            }
            BAR_ARRIVE(4 + ob_buf, 320);                    // OUT_FREE[buf]
        }
        g_I[b * UN + n0 + u0]     = Ia;
        g_I[b * UN + n0 + u0 + 1] = Ib;
    }
}

// ---------------- epilogue: Ubias, Z, P, D, Y (k-split, all fused) ------------
// grid (64, 4): 4 groups of 64 units. block 256 = 64 units x 4 kslices.
__global__ void epilogue_kernel(const float* __restrict__ U,
                                const float* __restrict__ X,
                                const float* __restrict__ R_z,
                                const float* __restrict__ b_z,
                                const float* __restrict__ R_b,
                                const float* __restrict__ W_p,
                                const float* __restrict__ W_d,
                                float* __restrict__ out) {
    __shared__ float usm[K_SZ];
    __shared__ float xl[K_SZ];
    __shared__ float dx[K_SZ];
    __shared__ float red[6][4][72];
    const int b  = blockIdx.x;
    const int cl = threadIdx.x & 63;
    const int ks = threadIdx.x >> 6;
    const int u  = blockIdx.y * 64 + cl;

    const float* xlast = X + ((size_t)b * T_SZ + (T_SZ - 1)) * K_SZ;
    const float* xprev = X + ((size_t)b * T_SZ + (T_SZ - 2)) * K_SZ;
    if (threadIdx.x < K_SZ) {
        float a = xlast[threadIdx.x];
        usm[threadIdx.x] = U[b * K_SZ + threadIdx.x];
        xl[threadIdx.x] = a;
        dx[threadIdx.x] = a - xprev[threadIdx.x];
    }
    __syncthreads();

    float aUb = 0.0f, aZp = 0.0f, aZi = 0.0f, aZd = 0.0f, aP = 0.0f, aD = 0.0f;
    const float* Rb = R_b + (size_t)(ks * 64) * UN + u;
    const float* Rz = R_z + (size_t)(ks * 64) * 768 + 3 * u;
    const float* Wp = W_p + (size_t)(ks * 64) * UN + u;
    const float* Wd = W_d + (size_t)(ks * 64) * UN + u;
    #pragma unroll 8
    for (int k = 0; k < 64; k++) {
        float uv = usm[ks * 64 + k];
        float xv = xl[ks * 64 + k];
        float dv = dx[ks * 64 + k];
        aUb = fmaf(uv, Rb[(size_t)k * UN], aUb);
        aZp = fmaf(uv, Rz[(size_t)k * 768],     aZp);
        aZi = fmaf(uv, Rz[(size_t)k * 768 + 1], aZi);
        aZd = fmaf(uv, Rz[(size_t)k * 768 + 2], aZd);
        aP  = fmaf(xv, Wp[(size_t)k * UN], aP);
        aD  = fmaf(dv, Wd[(size_t)k * UN], aD);
    }
    red[0][ks][cl] = aUb; red[1][ks][cl] = aZp; red[2][ks][cl] = aZi;
    red[3][ks][cl] = aZd; red[4][ks][cl] = aP;  red[5][ks][cl] = aD;
    __syncthreads();

    if (ks == 0) {
        float Ub = red[0][0][cl] + red[0][1][cl] + red[0][2][cl] + red[0][3][cl];
        float Zp = red[1][0][cl] + red[1][1][cl] + red[1][2][cl] + red[1][3][cl] + b_z[3 * u];
        float Zi = red[2][0][cl] + red[2][1][cl] + red[2][2][cl] + red[2][3][cl] + b_z[3 * u + 1];
        float Zd = red[3][0][cl] + red[3][1][cl] + red[3][2][cl] + red[3][3][cl] + b_z[3 * u + 2];
        float Pt = red[4][0][cl] + red[4][1][cl] + red[4][2][cl] + red[4][3][cl] + Ub;
        float Dt = red[5][0][cl] + red[5][1][cl] + red[5][2][cl] + red[5][3][cl];
        float P  = softsign_exact(Pt);
        float Dv = softsign_exact(Dt);
        float I  = g_I[b * UN + u];
        out[b * UN + u] = Zp * P + Zi * I + Zd * Dv;
    }
}

// ---------------- launcher ----------------
extern "C" void kernel_launch(void* const* d_in, const int* in_sizes, int n_in,
                              void* d_out, int out_size) {
    const float* U   = (const float*)d_in[0];
    const float* X   = (const float*)d_in[1];
    const float* R_z = (const float*)d_in[2];
    const float* b_z = (const float*)d_in[3];
    const float* R_0 = (const float*)d_in[4];
    const float* b_0 = (const float*)d_in[5];
    const float* R_b = (const float*)d_in[6];
    const float* W_p = (const float*)d_in[7];
    const float* W_i = (const float*)d_in[8];
    const float* W_d = (const float*)d_in[9];
    float* out = (float*)d_out;

    cudaFuncSetAttribute(fused_kernel,
                         cudaFuncAttributeMaxDynamicSharedMemorySize, FUSED_SMEM);

    fused_kernel<<<2 * B_SZ, 384, FUSED_SMEM>>>(U, X, W_i, R_0, b_0);
    epilogue_kernel<<<dim3(B_SZ, 4), 256>>>(U, X, R_z, b_z, R_b, W_p, W_d, out);
}

// round 9
// speedup vs baseline: 2.3863x; 1.2077x over previous
#include <cuda_runtime.h>
#include <cuda_bf16.h>
#include <mma.h>
#include <cstdint>

#define B_SZ 64
#define T_SZ 2048
#define K_SZ 256      // U_dim == X_dim
#define UN   256      // units

static __device__ __forceinline__ float softsign_exact(float z) {
    return z / (1.0f + fabsf(z));
}

#define BAR_SYNC(id, cnt)   asm volatile("bar.sync %0, %1;"   :: "r"(id), "r"(cnt) : "memory")
#define BAR_ARRIVE(id, cnt) asm volatile("bar.arrive %0, %1;" :: "r"(id), "r"(cnt) : "memory")

// ======= single fused kernel: GEMM + softsign scan + all GEMV epilogues =======
// 128 CTAs: b = blockIdx.x>>1, n0 = (blockIdx.x&1)*128. blockDim=384:
//   tid [0,256)   : GEMM warps, pure LDSM+HMMA (32x32 warp tiles)
//   tid [256,320) : A staging warps (LDG X fp32 -> hi/lo bf16 split -> STS)
//   tid [320,384) : scan warps (2 u-chains per thread) + I0 + all output GEMVs
// Barriers (count 320 = 10 warps, one arrive-phase per sync-phase each):
//   OUT_READY[buf]=2+buf, OUT_FREE[buf]=4+buf, A_READY[buf]=6+buf, A_FREE[buf]=8+buf
#define TM 64
#define TN 128
#define KC 32
#define A_LD 40      // 32 + 8 pad
#define B_LD 136     // 128 + 8 pad
#define O_LD 136

#define A_HALF  (TM * A_LD * 2)                   // 5120 B (one of hi/lo)
#define OFF_BHI 0
#define OFF_BLO (K_SZ * B_LD * 2)                 // 69632
#define OFF_A   (2 * (K_SZ * B_LD * 2))           // 139264
#define OFF_OUT (OFF_A + 4 * A_HALF)              // 159744
#define OUT_ELE (TM * O_LD)                       // floats per buffer
#define FUSED_SMEM (OFF_OUT + 2 * OUT_ELE * 4)    // 229376 bytes

#define NCHUNK (T_SZ / TM)        // 32
#define NKC    (K_SZ / KC)        // 8
#define NSTEP  (NCHUNK * NKC)     // 256

static __device__ __forceinline__ void split4(float4 v, uint2& hv, uint2& lv) {
    __nv_bfloat162 h01, h23, l01, l23;
    h01.x = __float2bfloat16(v.x); h01.y = __float2bfloat16(v.y);
    h23.x = __float2bfloat16(v.z); h23.y = __float2bfloat16(v.w);
    l01.x = __float2bfloat16(v.x - __bfloat162float(h01.x));
    l01.y = __float2bfloat16(v.y - __bfloat162float(h01.y));
    l23.x = __float2bfloat16(v.z - __bfloat162float(h23.x));
    l23.y = __float2bfloat16(v.w - __bfloat162float(h23.y));
    hv.x = *reinterpret_cast<uint32_t*>(&h01);
    hv.y = *reinterpret_cast<uint32_t*>(&h23);
    lv.x = *reinterpret_cast<uint32_t*>(&l01);
    lv.y = *reinterpret_cast<uint32_t*>(&l23);
}

__global__ void __launch_bounds__(384, 1) fused_kernel(
        const float* __restrict__ U,
        const float* __restrict__ X,
        const float* __restrict__ W_i,
        const float* __restrict__ R_0,
        const float* __restrict__ b_0,
        const float* __restrict__ R_z,
        const float* __restrict__ b_z,
        const float* __restrict__ R_b,
        const float* __restrict__ W_p,
        const float* __restrict__ W_d,
        float* __restrict__ out) {
    using namespace nvcuda;
    extern __shared__ __align__(16) char smc[];
    __nv_bfloat16* const Bhi  = reinterpret_cast<__nv_bfloat16*>(smc + OFF_BHI);
    __nv_bfloat16* const Blo  = reinterpret_cast<__nv_bfloat16*>(smc + OFF_BLO);
    float*         const outs = reinterpret_cast<float*>(smc + OFF_OUT);

    const int tid = threadIdx.x;
    const int b   = blockIdx.x >> 1;
    const int n0  = (blockIdx.x & 1) * TN;
    const float* const Xb = X + (size_t)b * T_SZ * K_SZ;

    // ---- stage resident W half as hi/lo bf16 (warps 0-9; scan warps skip) ----
    if (tid < 320) {
        for (int idx = tid; idx < K_SZ * (TN / 4); idx += 320) {   // 8192 float4
            int row = idx >> 5, c4 = idx & 31;
            float4 v = *reinterpret_cast<const float4*>(W_i + (size_t)row * UN + n0 + c4 * 4);
            uint2 hv, lv;
            split4(v, hv, lv);
            *reinterpret_cast<uint2*>(&Bhi[row * B_LD + c4 * 4]) = hv;
            *reinterpret_cast<uint2*>(&Blo[row * B_LD + c4 * 4]) = lv;
        }
    }
    __syncthreads();

    if (tid < 256) {
        // ======================= GEMM warps (pure compute) =======================
        const int wid = tid >> 5;
        const int wm  = wid >> 2;        // 0..1 : rows of 32
        const int wn  = wid & 3;         // 0..3 : cols of 32

        wmma::fragment<wmma::accumulator, 16, 16, 16, float> acc[2][2];
        #pragma unroll
        for (int i = 0; i < 2; i++)
            #pragma unroll
            for (int j = 0; j < 2; j++) wmma::fill_fragment(acc[i][j], 0.0f);

        #pragma unroll 1
        for (int step = 0; step < NSTEP; step++) {
            const int c    = step >> 3;
            const int kc   = step & 7;
            const int abuf = step & 1;
            __nv_bfloat16* const Ah = reinterpret_cast<__nv_bfloat16*>(
                smc + OFF_A + abuf * 2 * A_HALF);
            __nv_bfloat16* const Al = reinterpret_cast<__nv_bfloat16*>(
                smc + OFF_A + abuf * 2 * A_HALF + A_HALF);

            BAR_SYNC(6 + abuf, 320);     // A_READY[abuf]

            #pragma unroll
            for (int kk = 0; kk < KC; kk += 16) {
                const int krow = kc * KC + kk;
                wmma::fragment<wmma::matrix_a, 16, 16, 16, __nv_bfloat16, wmma::row_major> ah[2], al[2];
                wmma::fragment<wmma::matrix_b, 16, 16, 16, __nv_bfloat16, wmma::row_major> bh[2], bl[2];
                #pragma unroll
                for (int i = 0; i < 2; i++) {
                    wmma::load_matrix_sync(ah[i], &Ah[(wm * 32 + i * 16) * A_LD + kk], A_LD);
                    wmma::load_matrix_sync(al[i], &Al[(wm * 32 + i * 16) * A_LD + kk], A_LD);
                }
                #pragma unroll
                for (int j = 0; j < 2; j++) {
                    wmma::load_matrix_sync(bh[j], &Bhi[krow * B_LD + wn * 32 + j * 16], B_LD);
                    wmma::load_matrix_sync(bl[j], &Blo[krow * B_LD + wn * 32 + j * 16], B_LD);
                }
                #pragma unroll
                for (int i = 0; i < 2; i++)
                    #pragma unroll
                    for (int j = 0; j < 2; j++) {
                        wmma::mma_sync(acc[i][j], ah[i], bh[j], acc[i][j]);   // Xhi*Whi
                        wmma::mma_sync(acc[i][j], al[i], bh[j], acc[i][j]);   // Xlo*Whi
                        wmma::mma_sync(acc[i][j], ah[i], bl[j], acc[i][j]);   // Xhi*Wlo
                    }
            }
            BAR_ARRIVE(8 + abuf, 320);   // A_FREE[abuf]

            if (kc == 7) {
                const int ob_buf = c & 1;
                if (c >= 2) BAR_SYNC(4 + ob_buf, 320);      // OUT_FREE[buf]
                float* ob = outs + ob_buf * OUT_ELE;
                #pragma unroll
                for (int i = 0; i < 2; i++)
                    #pragma unroll
                    for (int j = 0; j < 2; j++) {
                        wmma::store_matrix_sync(&ob[(wm * 32 + i * 16) * O_LD + wn * 32 + j * 16],
                                                acc[i][j], O_LD, wmma::mem_row_major);
                        wmma::fill_fragment(acc[i][j], 0.0f);
                    }
                BAR_ARRIVE(2 + ob_buf, 320);                // OUT_READY[buf]
            }
        }
    } else if (tid < 320) {
        // ======================= A staging warps =======================
        const int st = tid - 256;        // 0..63
        float4 xr[8];
        int rowv[8], c4v[8];
        #pragma unroll
        for (int r = 0; r < 8; r++) {
            int i = r * 64 + st;
            rowv[r] = i >> 3;
            c4v[r]  = i & 7;
        }
        #pragma unroll
        for (int r = 0; r < 8; r++)
            xr[r] = *reinterpret_cast<const float4*>(
                Xb + (size_t)rowv[r] * K_SZ + c4v[r] * 4);

        #pragma unroll 1
        for (int step = 0; step < NSTEP; step++) {
            const int abuf = step & 1;
            __nv_bfloat16* const Ah = reinterpret_cast<__nv_bfloat16*>(
                smc + OFF_A + abuf * 2 * A_HALF);
            __nv_bfloat16* const Al = reinterpret_cast<__nv_bfloat16*>(
                smc + OFF_A + abuf * 2 * A_HALF + A_HALF);

            if (step >= 2) BAR_SYNC(8 + abuf, 320);   // A_FREE[abuf]
            #pragma unroll
            for (int r = 0; r < 8; r++) {
                uint2 hv, lv;
                split4(xr[r], hv, lv);
                *reinterpret_cast<uint2*>(&Ah[rowv[r] * A_LD + c4v[r] * 4]) = hv;
                *reinterpret_cast<uint2*>(&Al[rowv[r] * A_LD + c4v[r] * 4]) = lv;
            }
            BAR_ARRIVE(6 + abuf, 320);                // A_READY[abuf]

            if (step + 1 < NSTEP) {
                const int nc  = (step + 1) >> 3;
                const int nkc = (step + 1) & 7;
                const float* src = Xb + (size_t)(nc * TM) * K_SZ + nkc * KC;
                #pragma unroll
                for (int r = 0; r < 8; r++)
                    xr[r] = *reinterpret_cast<const float4*>(
                        src + (size_t)rowv[r] * K_SZ + c4v[r] * 4);
            }
        }
    } else {
        // ============ scan warps: I recurrence + all output GEMVs ============
        const int u0 = (tid - 320) * 2;   // 0,2,..,126 (local)
        const int ug = n0 + u0;           // global unit column (even)

        // I0 = U@R_0[:, ug(+1)] + b_0 (overlapped with GEMM pipeline startup)
        float Ia = b_0[ug];
        float Ib = b_0[ug + 1];
        {
            const float* R0c = R_0 + ug;            // R_0 is [K_SZ][512]
            const float* Ub  = U + (size_t)b * K_SZ;
            #pragma unroll 8
            for (int k = 0; k < K_SZ; k++) {
                float uv = Ub[k];
                Ia = fmaf(uv, R0c[(size_t)k * 512],     Ia);
                Ib = fmaf(uv, R0c[(size_t)k * 512 + 1], Ib);
            }
        }

        // epilogue accumulators (computed in k-slices of 8 per chunk)
        float ub_a = 0.f, ub_b = 0.f;
        float zp_a = b_z[3 * ug],     zi_a = b_z[3 * ug + 1], zd_a = b_z[3 * ug + 2];
        float zp_b = b_z[3 * ug + 3], zi_b = b_z[3 * ug + 4], zd_b = b_z[3 * ug + 5];
        float p_a = 0.f, p_b = 0.f, d_a = 0.f, d_b = 0.f;
        const float* const Ub   = U + (size_t)b * K_SZ;
        const float* const xlp  = Xb + (size_t)(T_SZ - 1) * K_SZ;
        const float* const xpp  = Xb + (size_t)(T_SZ - 2) * K_SZ;

        #pragma unroll 1
        for (int c = 0; c < NCHUNK; c++) {
            const int ob_buf = c & 1;
            BAR_SYNC(2 + ob_buf, 320);                      // OUT_READY[buf]
            const float* ob = outs + ob_buf * OUT_ELE;
            const float2* obp = reinterpret_cast<const float2*>(ob) + (u0 >> 1);
            float2 v  = obp[0];
            float2 vn = obp[O_LD / 2];
            #pragma unroll 8
            for (int t = 0; t < TM; t++) {
                float za = Ia + v.x;
                float zb = Ib + v.y;
                v = vn;
                if (t + 2 < TM) vn = obp[(size_t)(t + 2) * (O_LD / 2)];
                Ia = __fdividef(za, 1.0f + fabsf(za));
                Ib = __fdividef(zb, 1.0f + fabsf(zb));
            }
            BAR_ARRIVE(4 + ob_buf, 320);                    // OUT_FREE[buf]

            // ---- epilogue k-slice [8c, 8c+8) (never delays GEMM) ----
            #pragma unroll
            for (int kk = 0; kk < 8; kk++) {
                const int k = c * 8 + kk;
                float uv  = Ub[k];
                float xlv = xlp[k];
                float dxv = xlv - xpp[k];
                float2 rb  = *reinterpret_cast<const float2*>(R_b + (size_t)k * UN + ug);
                float2 rz0 = *reinterpret_cast<const float2*>(R_z + (size_t)k * 768 + 3 * ug);
                float2 rz1 = *reinterpret_cast<const float2*>(R_z + (size_t)k * 768 + 3 * ug + 2);
                float2 rz2 = *reinterpret_cast<const float2*>(R_z + (size_t)k * 768 + 3 * ug + 4);
                float2 wp  = *reinterpret_cast<const float2*>(W_p + (size_t)k * UN + ug);
                float2 wd  = *reinterpret_cast<const float2*>(W_d + (size_t)k * UN + ug);
                ub_a = fmaf(uv, rb.x, ub_a);   ub_b = fmaf(uv, rb.y, ub_b);
                zp_a = fmaf(uv, rz0.x, zp_a);  zi_a = fmaf(uv, rz0.y, zi_a);
                zd_a = fmaf(uv, rz1.x, zd_a);  zp_b = fmaf(uv, rz1.y, zp_b);
                zi_b = fmaf(uv, rz2.x, zi_b);  zd_b = fmaf(uv, rz2.y, zd_b);
                p_a  = fmaf(xlv, wp.x, p_a);   p_b  = fmaf(xlv, wp.y, p_b);
                d_a  = fmaf(dxv, wd.x, d_a);   d_b  = fmaf(dxv, wd.y, d_b);
            }
        }

        // final outputs
        float Pa = softsign_exact(ub_a + p_a);
        float Pb = softsign_exact(ub_b + p_b);
        float Da = softsign_exact(d_a);
        float Db = softsign_exact(d_b);
        float2 r;
        r.x = zp_a * Pa + zi_a * Ia + zd_a * Da;
        r.y = zp_b * Pb + zi_b * Ib + zd_b * Db;
        *reinterpret_cast<float2*>(out + (size_t)b * UN + ug) = r;
    }
}

// ---------------- launcher ----------------
extern "C" void kernel_launch(void* const* d_in, const int* in_sizes, int n_in,
                              void* d_out, int out_size) {
    const float* U   = (const float*)d_in[0];
    const float* X   = (const float*)d_in[1];
    const float* R_z = (const float*)d_in[2];
    const float* b_z = (const float*)d_in[3];
    const float* R_0 = (const float*)d_in[4];
    const float* b_0 = (const float*)d_in[5];
    const float* R_b = (const float*)d_in[6];
    const float* W_p = (const float*)d_in[7];
    const float* W_i = (const float*)d_in[8];
    const float* W_d = (const float*)d_in[9];
    float* out = (float*)d_out;

    cudaFuncSetAttribute(fused_kernel,
                         cudaFuncAttributeMaxDynamicSharedMemorySize, FUSED_SMEM);

    fused_kernel<<<2 * B_SZ, 384, FUSED_SMEM>>>(U, X, W_i, R_0, b_0,
                                                R_z, b_z, R_b, W_p, W_d, out);
}